// round 9
// baseline (speedup 1.0000x reference)
#include <cuda_runtime.h>
#include <cuda_bf16.h>
#include <cstdint>
#include <cmath>

// ---------------- problem constants ----------------
#define Bv     64
#define Cv     3
#define IMGv   224
#define Pv     16
#define Sv     8
#define Gv     14
#define NPv    196
#define Nv     197
#define DIMv   384
#define DEPTHv 12
#define Hv     12
#define DHv    32
#define INNERv 384
#define MLPv   1536
#define NCLSv  1000
#define PDv    1792
#define TOK    (Bv*Nv)      // 12608
#define MP     (Bv*NPv)     // 12544
#define EPSv   1e-5f

#define K3_DIM (3*DIMv)     // 1152
#define K3_MLP (3*MLPv)     // 4608
#define K3_PD  (3*PDv)      // 5376

// ---------------- scratch (device globals; no allocation allowed) ----------------
__device__ float g_mean [Bv * IMGv * IMGv];
__device__ float g_x    [TOK * DIMv];
__device__ float g_qkv  [TOK * 3 * INNERv];

__device__ __nv_bfloat16 a2_patch[(size_t)MP  * K3_PD];
__device__ __nv_bfloat16 a2_h    [(size_t)TOK * K3_DIM];
__device__ __nv_bfloat16 a2_o    [(size_t)TOK * K3_DIM];
__device__ __nv_bfloat16 a2_ff   [(size_t)TOK * K3_MLP];
__device__ __nv_bfloat16 a2_cls  [Bv * K3_DIM];

__device__ __nv_bfloat16 w2_patch[(size_t)DIMv  * K3_PD];
__device__ __nv_bfloat16 w2_qkv  [(size_t)DEPTHv * 3*INNERv * K3_DIM];
__device__ __nv_bfloat16 w2_out  [(size_t)DEPTHv * DIMv     * K3_DIM];
__device__ __nv_bfloat16 w2_ff1  [(size_t)DEPTHv * MLPv     * K3_DIM];
__device__ __nv_bfloat16 w2_ff2  [(size_t)DEPTHv * DIMv     * K3_MLP];
__device__ __nv_bfloat16 w2_head [(size_t)NCLSv * K3_DIM];

// ---------------- small helpers ----------------
__device__ __forceinline__ float gelu_exact(float x) {
    return 0.5f * x * (1.0f + erff(x * 0.70710678118654752440f));
}
__device__ __forceinline__ void split2(float v, __nv_bfloat16& hi, __nv_bfloat16& lo) {
    hi = __float2bfloat16(v);
    lo = __float2bfloat16(v - __bfloat162float(hi));
}
__device__ __forceinline__ uint32_t smem_u32(const void* p) {
    uint32_t a;
    asm("{ .reg .u64 t; cvta.to.shared.u64 t, %1; cvt.u32.u64 %0, t; }" : "=r"(a) : "l"(p));
    return a;
}
__device__ __forceinline__ void cp16(uint32_t dst, const void* src, uint32_t srcsize) {
    asm volatile("cp.async.cg.shared.global [%0], [%1], 16, %2;"
                 :: "r"(dst), "l"(src), "r"(srcsize) : "memory");
}
#define CP_COMMIT() asm volatile("cp.async.commit_group;" ::: "memory")
#define CP_WAIT2()  asm volatile("cp.async.wait_group 2;" ::: "memory")

__device__ __forceinline__ void ldsm4(uint32_t* r, uint32_t addr) {
    asm volatile("ldmatrix.sync.aligned.m8n8.x4.shared.b16 {%0,%1,%2,%3}, [%4];"
                 : "=r"(r[0]), "=r"(r[1]), "=r"(r[2]), "=r"(r[3]) : "r"(addr));
}
__device__ __forceinline__ void mma16816(float* c, const uint32_t* a,
                                         uint32_t b0, uint32_t b1) {
    asm volatile(
        "mma.sync.aligned.m16n8k16.row.col.f32.bf16.bf16.f32 "
        "{%0,%1,%2,%3}, {%4,%5,%6,%7}, {%8,%9}, {%0,%1,%2,%3};"
        : "+f"(c[0]), "+f"(c[1]), "+f"(c[2]), "+f"(c[3])
        : "r"(a[0]), "r"(a[1]), "r"(a[2]), "r"(a[3]), "r"(b0), "r"(b1));
}

// ---------------- preprocessing kernels ----------------
__global__ void mean_kernel(const float* __restrict__ img) {
    int idx = blockIdx.x * blockDim.x + threadIdx.x;
    if (idx >= Bv * IMGv * IMGv) return;
    int b = idx / (IMGv * IMGv);
    int yx = idx % (IMGv * IMGv);
    const float* p = img + (size_t)b * Cv * IMGv * IMGv + yx;
    g_mean[idx] = (p[0] + p[IMGv * IMGv] + p[2 * IMGv * IMGv]) * (1.0f / 3.0f);
}

__global__ void patch_build_kernel(const float* __restrict__ img) {
    int idx = blockIdx.x * blockDim.x + threadIdx.x;
    if (idx >= MP * PDv) return;
    int pd = idx % PDv;
    int n  = (idx / PDv) % NPv;
    int b  = idx / (PDv * NPv);
    int c  = pd % 7;
    int pp = pd / 7;
    int px = pp % Pv, py = pp / Pv;
    int gy = n / Gv, gx = n % Gv;
    int y = gy * Pv + py, x = gx * Pv + px;
    float v;
    if (c < 3) {
        v = img[(((size_t)b * Cv + c) * IMGv + y) * IMGv + x];
    } else {
        int yy = y, xx = x;
        if      (c == 3) xx = x - Sv;
        else if (c == 4) xx = x + Sv;
        else if (c == 5) yy = y - Sv;
        else             yy = y + Sv;
        v = (xx < 0 || xx >= IMGv || yy < 0 || yy >= IMGv)
                ? 0.0f : g_mean[((size_t)b * IMGv + yy) * IMGv + xx];
    }
    __nv_bfloat16 hi, lo; split2(v, hi, lo);
    size_t row = (size_t)(b * NPv + n) * K3_PD;
    a2_patch[row + pd]            = hi;
    a2_patch[row + PDv + pd]      = lo;
    a2_patch[row + 2 * PDv + pd]  = hi;
}

__global__ void cls_init_kernel(const float* __restrict__ cls_tok,
                                const float* __restrict__ pos) {
    int d = threadIdx.x;
    int b = blockIdx.x;
    g_x[(size_t)b * Nv * DIMv + d] = cls_tok[d] + pos[d];
}

// weight convert: src [L][Nr,K] fp32 -> dst [L][Nr,3K] bf16  ([hi|hi|lo])
__global__ void convw_kernel(const float* __restrict__ src, __nv_bfloat16* __restrict__ dst,
                             int Nr, int K) {
    int idx = blockIdx.x * 256 + threadIdx.x;
    if (idx >= Nr * K) return;
    src += (size_t)blockIdx.y * Nr * K;
    dst += (size_t)blockIdx.y * Nr * 3 * K;
    int n = idx / K, k = idx % K;
    __nv_bfloat16 hi, lo; split2(src[idx], hi, lo);
    size_t r = (size_t)n * 3 * K;
    dst[r + k]         = hi;
    dst[r + K + k]     = hi;
    dst[r + 2 * K + k] = lo;
}

// ---------------- layernorm -> split-bf16 activation ([hi|lo|hi]) ----------------
__global__ void __launch_bounds__(128)
ln_split_kernel(const float* __restrict__ x, const float* __restrict__ g,
                const float* __restrict__ bta, __nv_bfloat16* __restrict__ out,
                long in_stride)
{
    long r = blockIdx.x;
    const float* xr = x + r * in_stride;
    int t = threadIdx.x;
    float v0 = xr[t], v1 = xr[t + 128], v2 = xr[t + 256];
    float s1 = v0 + v1 + v2;
    float s2 = v0 * v0 + v1 * v1 + v2 * v2;
    #pragma unroll
    for (int o = 16; o; o >>= 1) {
        s1 += __shfl_xor_sync(0xFFFFFFFFu, s1, o);
        s2 += __shfl_xor_sync(0xFFFFFFFFu, s2, o);
    }
    __shared__ float sh[8];
    int w = t >> 5;
    if ((t & 31) == 0) { sh[w] = s1; sh[4 + w] = s2; }
    __syncthreads();
    s1 = sh[0] + sh[1] + sh[2] + sh[3];
    s2 = sh[4] + sh[5] + sh[6] + sh[7];
    float mu  = s1 * (1.0f / DIMv);
    float var = s2 * (1.0f / DIMv) - mu * mu;
    float rs  = rsqrtf(var + EPSv);
    __nv_bfloat16* orow = out + r * (long)K3_DIM;
    #pragma unroll
    for (int q = 0; q < 3; q++) {
        int c = t + q * 128;
        float vv = (q == 0 ? v0 : (q == 1 ? v1 : v2));
        float y = (vv - mu) * rs * g[c] + bta[c];
        __nv_bfloat16 hi, lo; split2(y, hi, lo);
        orow[c]            = hi;
        orow[DIMv + c]     = lo;
        orow[2 * DIMv + c] = hi;
    }
}

// ---------------- attention: block per (b,h); writes split o ----------------
__global__ void __launch_bounds__(256)
attn2(const float* __restrict__ scale)
{
    __shared__ float Ks[Nv][DHv];
    __shared__ float Vs[Nv][DHv];
    int h = blockIdx.x % Hv;
    int b = blockIdx.x / Hv;
    const float* base = g_qkv + (size_t)b * Nv * (3 * INNERv) + h * DHv;

    for (int idx = threadIdx.x; idx < Nv * 8; idx += 256) {
        int r = idx >> 3;
        int c = (idx & 7) * 4;
        const float* row = base + (size_t)r * (3 * INNERv);
        *(float4*)&Ks[r][c] = *(const float4*)(row + INNERv + c);
        *(float4*)&Vs[r][c] = *(const float4*)(row + 2 * INNERv + c);
    }
    __syncthreads();

    int i = threadIdx.x;
    if (i >= Nv) return;
    float sc = scale[h];
    const float* qrow = base + (size_t)i * (3 * INNERv);
    float q[DHv];
    #pragma unroll
    for (int c = 0; c < DHv; c++) q[c] = qrow[c] * sc;

    float m = -INFINITY, s = 0.0f;
    float acc[DHv];
    #pragma unroll
    for (int c = 0; c < DHv; c++) acc[c] = 0.0f;

    for (int j = 0; j < Nv; j++) {
        if (j == i) continue;
        float d = 0.0f;
        #pragma unroll
        for (int c = 0; c < DHv; c++) d = fmaf(q[c], Ks[j][c], d);
        float nm = fmaxf(m, d);
        float f  = __expf(m - nm);
        float p  = __expf(d - nm);
        s = s * f + p;
        #pragma unroll
        for (int c = 0; c < DHv; c++) acc[c] = fmaf(acc[c], f, p * Vs[j][c]);
        m = nm;
    }
    float inv = 1.0f / s;
    __nv_bfloat16* o = a2_o + (size_t)(b * Nv + i) * K3_DIM + h * DHv;
    #pragma unroll
    for (int c = 0; c < DHv; c++) {
        __nv_bfloat16 hi, lo; split2(acc[c] * inv, hi, lo);
        o[c]            = hi;
        o[DIMv + c]     = lo;
        o[2 * DIMv + c] = hi;
    }
}

// ---------------- HMMA split-bf16 GEMM: C = A2[M,3K] * W2[N,3K]^T ----------------
// CTA tile 128x128, 4 warps of 64x64, 128 threads, BK=32, 4-stage cp.async ring.
#define FLAG_GELU  1
#define FLAG_REMAP 2
#define FLAG_SPLIT 4
#define HSTRIDE 40                       // halves per smem row (80B, conflict-free)
#define HS_B    (128 * HSTRIDE * 2)      // 10240B
#define STAGEB  (2 * 128 * HSTRIDE * 2)  // 20480B
#define NSTAGE  4
#define SMEM_DYN (NSTAGE * STAGEB)       // 81920B

__device__ __forceinline__ void store_pair(
    float v0, float v1, int orow, int gn, int Nn,
    const float* bias, const float* resid, const float* pos,
    float* Cf, __nv_bfloat16* Cs, int flags)
{
    if (bias) { v0 += bias[gn]; v1 += bias[gn + 1]; }
    if (flags & FLAG_GELU) { v0 = gelu_exact(v0); v1 = gelu_exact(v1); }
    if (pos) {
        const float* pp = pos + (size_t)(orow % Nv) * Nn + gn;
        v0 += pp[0]; v1 += pp[1];
    }
    if (resid) {
        const float* rr = resid + (size_t)orow * Nn + gn;
        v0 += rr[0]; v1 += rr[1];
    }
    if (flags & FLAG_SPLIT) {
        __nv_bfloat16 h0, l0, h1, l1;
        split2(v0, h0, l0); split2(v1, h1, l1);
        __nv_bfloat16* p = Cs + (size_t)orow * 3 * Nn + gn;
        *(__nv_bfloat162*)(p)          = __halves2bfloat162(h0, h1);
        *(__nv_bfloat162*)(p + Nn)     = __halves2bfloat162(l0, l1);
        *(__nv_bfloat162*)(p + 2 * Nn) = __halves2bfloat162(h0, h1);
    } else {
        *(float2*)(Cf + (size_t)orow * Nn + gn) = make_float2(v0, v1);
    }
}

__global__ void __launch_bounds__(128, 2)
hm_gemm(const __nv_bfloat16* __restrict__ A, const __nv_bfloat16* __restrict__ W,
        const float* __restrict__ bias, const float* __restrict__ resid,
        const float* __restrict__ pos, float* __restrict__ Cf,
        __nv_bfloat16* __restrict__ Cs,
        int M, int Nn, int K3, int flags)
{
    extern __shared__ __align__(16) char sm[];
    uint32_t sbase = smem_u32(sm);
    int tid = threadIdx.x, lane = tid & 31, wid = tid >> 5;   // 4 warps
    int m0 = blockIdx.y * 128, n0 = blockIdx.x * 128;
    int wr = wid >> 1, wc = wid & 1;     // warp tile: 64(M) x 64(N)

    float c[4][8][4];
    #pragma unroll
    for (int i = 0; i < 4; i++)
        #pragma unroll
        for (int j = 0; j < 8; j++)
            #pragma unroll
            for (int q = 0; q < 4; q++) c[i][j][q] = 0.0f;

    const int rbase = tid >> 2;          // 0..31
    const int kseg  = (tid & 3) * 8;     // halves

    const int nk = K3 / 32;

    auto load_stage = [&](int slot, int ch) {
        uint32_t sa = sbase + slot * STAGEB;
        int kk = ch * 32;
        #pragma unroll
        for (int i = 0; i < 4; i++) {
            int r = rbase + i * 32;
            uint32_t dst = sa + (uint32_t)(r * HSTRIDE + kseg) * 2;
            const void* src = A + (size_t)(m0 + r) * K3 + kk + kseg;
            cp16(dst, src, (m0 + r < M) ? 16u : 0u);
        }
        #pragma unroll
        for (int i = 0; i < 4; i++) {
            int r = rbase + i * 32;
            uint32_t dst = sa + HS_B + (uint32_t)(r * HSTRIDE + kseg) * 2;
            const void* src = W + (size_t)(n0 + r) * K3 + kk + kseg;
            cp16(dst, src, (n0 + r < Nn) ? 16u : 0u);
        }
        CP_COMMIT();
    };

    #pragma unroll
    for (int s = 0; s < NSTAGE - 1; s++) load_stage(s, s);   // nk >= 3 always

    for (int ch = 0; ch < nk; ch++) {
        CP_WAIT2();
        __syncthreads();
        if (ch + NSTAGE - 1 < nk) load_stage((ch + NSTAGE - 1) & 3, ch + NSTAGE - 1);
        else CP_COMMIT();

        uint32_t sa = sbase + (ch & 3) * STAGEB;
        #pragma unroll
        for (int ko = 0; ko < 2; ko++) {
            int col = ko * 16 + ((lane >> 4) << 3);
            uint32_t a[4][4];
            #pragma unroll
            for (int mf = 0; mf < 4; mf++) {
                int row = wr * 64 + mf * 16 + (lane & 15);
                ldsm4(a[mf], sa + (uint32_t)(row * HSTRIDE + col) * 2);
            }
            uint32_t b[4][4];
            #pragma unroll
            for (int p = 0; p < 4; p++) {
                int row = wc * 64 + p * 16 + (lane & 15);
                ldsm4(b[p], sa + HS_B + (uint32_t)(row * HSTRIDE + col) * 2);
            }
            #pragma unroll
            for (int mf = 0; mf < 4; mf++)
                #pragma unroll
                for (int nf = 0; nf < 8; nf++) {
                    int p = nf >> 1, q = nf & 1;
                    mma16816(c[mf][nf], a[mf], b[p][q], b[p][2 + q]);
                }
        }
    }

    // ---- epilogue ----
    #pragma unroll
    for (int mf = 0; mf < 4; mf++) {
        int r0 = m0 + wr * 64 + mf * 16 + (lane >> 2);
        #pragma unroll
        for (int nf = 0; nf < 8; nf++) {
            int gn = n0 + wc * 64 + nf * 8 + (lane & 3) * 2;
            if (gn >= Nn) continue;
            if (r0 < M) {
                int orow = r0;
                if (flags & FLAG_REMAP) { int b = r0 / NPv; orow = r0 + b + 1; }
                store_pair(c[mf][nf][0], c[mf][nf][1], orow, gn, Nn,
                           bias, resid, pos, Cf, Cs, flags);
            }
            int r1 = r0 + 8;
            if (r1 < M) {
                int orow = r1;
                if (flags & FLAG_REMAP) { int b = r1 / NPv; orow = r1 + b + 1; }
                store_pair(c[mf][nf][2], c[mf][nf][3], orow, gn, Nn,
                           bias, resid, pos, Cf, Cs, flags);
            }
        }
    }
}

// ---------------- host side ----------------
static inline void run_hm(const __nv_bfloat16* A, const __nv_bfloat16* W,
                          const float* bias, const float* resid, const float* pos,
                          float* Cf, __nv_bfloat16* Cs,
                          int M, int Nn, int K3, int flags)
{
    dim3 grid((Nn + 127) / 128, (M + 127) / 128);
    hm_gemm<<<grid, 128, SMEM_DYN>>>(A, W, bias, resid, pos, Cf, Cs, M, Nn, K3, flags);
}

extern "C" void kernel_launch(void* const* d_in, const int* in_sizes, int n_in,
                              void* d_out, int out_size)
{
    const float* img     = (const float*)d_in[0];
    const float* patch_w = (const float*)d_in[1];
    const float* patch_b = (const float*)d_in[2];
    const float* pos_emb = (const float*)d_in[3];
    const float* cls_tok = (const float*)d_in[4];
    const float* ln1_g   = (const float*)d_in[5];
    const float* ln1_b   = (const float*)d_in[6];
    const float* qkv_w   = (const float*)d_in[7];
    const float* scale   = (const float*)d_in[8];
    const float* out_w   = (const float*)d_in[9];
    const float* out_b   = (const float*)d_in[10];
    const float* ln2_g   = (const float*)d_in[11];
    const float* ln2_b   = (const float*)d_in[12];
    const float* ff_w1   = (const float*)d_in[13];
    const float* ff_b1   = (const float*)d_in[14];
    const float* ff_w2   = (const float*)d_in[15];
    const float* ff_b2   = (const float*)d_in[16];
    const float* lnf_g   = (const float*)d_in[17];
    const float* lnf_b   = (const float*)d_in[18];
    const float* head_w  = (const float*)d_in[19];
    const float* head_b  = (const float*)d_in[20];

    cudaFuncSetAttribute(hm_gemm, cudaFuncAttributeMaxDynamicSharedMemorySize, SMEM_DYN);

    float *xp, *qkvp;
    __nv_bfloat16 *a2p, *a2hp, *a2op, *a2fp, *a2cp;
    __nv_bfloat16 *w2p, *w2q, *w2o, *w2f1, *w2f2, *w2h;
    cudaGetSymbolAddress((void**)&xp,   g_x);
    cudaGetSymbolAddress((void**)&qkvp, g_qkv);
    cudaGetSymbolAddress((void**)&a2p,  a2_patch);
    cudaGetSymbolAddress((void**)&a2hp, a2_h);
    cudaGetSymbolAddress((void**)&a2op, a2_o);
    cudaGetSymbolAddress((void**)&a2fp, a2_ff);
    cudaGetSymbolAddress((void**)&a2cp, a2_cls);
    cudaGetSymbolAddress((void**)&w2p,  w2_patch);
    cudaGetSymbolAddress((void**)&w2q,  w2_qkv);
    cudaGetSymbolAddress((void**)&w2o,  w2_out);
    cudaGetSymbolAddress((void**)&w2f1, w2_ff1);
    cudaGetSymbolAddress((void**)&w2f2, w2_ff2);
    cudaGetSymbolAddress((void**)&w2h,  w2_head);

    {
        int n = Bv * IMGv * IMGv;
        mean_kernel<<<(n + 255) / 256, 256>>>(img);
        int np = MP * PDv;
        patch_build_kernel<<<(np + 255) / 256, 256>>>(img);
        int nw = DIMv * PDv;
        convw_kernel<<<dim3((nw + 255) / 256, 1), 256>>>(patch_w, w2p, DIMv, PDv);
        cls_init_kernel<<<Bv, DIMv>>>(cls_tok, pos_emb);
        int nq = 3 * INNERv * DIMv;
        convw_kernel<<<dim3((nq + 255) / 256, DEPTHv), 256>>>(qkv_w, w2q, 3 * INNERv, DIMv);
    }
    run_hm(a2p, w2p, patch_b, nullptr, pos_emb, xp, nullptr,
           MP, DIMv, K3_PD, FLAG_REMAP);

    {
        int n;
        n = DIMv * INNERv;
        convw_kernel<<<dim3((n + 255) / 256, DEPTHv), 256>>>(out_w, w2o, DIMv, INNERv);
        n = MLPv * DIMv;
        convw_kernel<<<dim3((n + 255) / 256, DEPTHv), 256>>>(ff_w1, w2f1, MLPv, DIMv);
        n = DIMv * MLPv;
        convw_kernel<<<dim3((n + 255) / 256, DEPTHv), 256>>>(ff_w2, w2f2, DIMv, MLPv);
        n = NCLSv * DIMv;
        convw_kernel<<<dim3((n + 255) / 256, 1), 256>>>(head_w, w2h, NCLSv, DIMv);
    }

    for (int L = 0; L < DEPTHv; L++) {
        ln_split_kernel<<<TOK, 128>>>(xp, ln1_g + L * DIMv, ln1_b + L * DIMv, a2hp, DIMv);
        run_hm(a2hp, w2q + (size_t)L * 3 * INNERv * K3_DIM, nullptr, nullptr, nullptr,
               qkvp, nullptr, TOK, 3 * INNERv, K3_DIM, 0);
        attn2<<<Bv * Hv, 256>>>(scale + L * Hv);
        run_hm(a2op, w2o + (size_t)L * DIMv * K3_DIM, out_b + L * DIMv, xp, nullptr,
               xp, nullptr, TOK, DIMv, K3_DIM, 0);
        ln_split_kernel<<<TOK, 128>>>(xp, ln2_g + L * DIMv, ln2_b + L * DIMv, a2hp, DIMv);
        run_hm(a2hp, w2f1 + (size_t)L * MLPv * K3_DIM, ff_b1 + L * MLPv, nullptr, nullptr,
               nullptr, a2fp, TOK, MLPv, K3_DIM, FLAG_GELU | FLAG_SPLIT);
        run_hm(a2fp, w2f2 + (size_t)L * DIMv * K3_MLP, ff_b2 + L * DIMv, xp, nullptr,
               xp, nullptr, TOK, DIMv, K3_MLP, 0);
    }

    // final LN on cls rows (row b = x[b*197*384]) -> split, then head
    ln_split_kernel<<<Bv, 128>>>(xp, lnf_g, lnf_b, a2cp, (long)Nv * DIMv);
    run_hm(a2cp, w2h, head_b, nullptr, nullptr, (float*)d_out, nullptr,
           Bv, NCLSv, K3_DIM, 0);
}

// round 10
// speedup vs baseline: 1.0165x; 1.0165x over previous
#include <cuda_runtime.h>
#include <cuda_bf16.h>
#include <cstdint>
#include <cmath>

// ---------------- problem constants ----------------
#define Bv     64
#define Cv     3
#define IMGv   224
#define Pv     16
#define Sv     8
#define Gv     14
#define NPv    196
#define Nv     197
#define DIMv   384
#define DEPTHv 12
#define Hv     12
#define DHv    32
#define INNERv 384
#define MLPv   1536
#define NCLSv  1000
#define PDv    1792
#define TOK    (Bv*Nv)      // 12608
#define MP     (Bv*NPv)     // 12544
#define EPSv   1e-5f

#define K3_DIM (3*DIMv)     // 1152
#define K3_MLP (3*MLPv)     // 4608
#define K3_PD  (3*PDv)      // 5376

#define NPERSIST 296        // 148 SMs x 2 CTAs

// ---------------- scratch (device globals; no allocation allowed) ----------------
__device__ float g_mean [Bv * IMGv * IMGv];
__device__ float g_x    [TOK * DIMv];
__device__ float g_qkv  [TOK * 3 * INNERv];

__device__ __nv_bfloat16 a2_patch[(size_t)MP  * K3_PD];
__device__ __nv_bfloat16 a2_h    [(size_t)TOK * K3_DIM];
__device__ __nv_bfloat16 a2_o    [(size_t)TOK * K3_DIM];
__device__ __nv_bfloat16 a2_ff   [(size_t)TOK * K3_MLP];
__device__ __nv_bfloat16 a2_cls  [Bv * K3_DIM];

__device__ __nv_bfloat16 w2_patch[(size_t)DIMv  * K3_PD];
__device__ __nv_bfloat16 w2_qkv  [(size_t)DEPTHv * 3*INNERv * K3_DIM];
__device__ __nv_bfloat16 w2_out  [(size_t)DEPTHv * DIMv     * K3_DIM];
__device__ __nv_bfloat16 w2_ff1  [(size_t)DEPTHv * MLPv     * K3_DIM];
__device__ __nv_bfloat16 w2_ff2  [(size_t)DEPTHv * DIMv     * K3_MLP];
__device__ __nv_bfloat16 w2_head [(size_t)NCLSv * K3_DIM];

// ---------------- small helpers ----------------
__device__ __forceinline__ float gelu_exact(float x) {
    return 0.5f * x * (1.0f + erff(x * 0.70710678118654752440f));
}
__device__ __forceinline__ void split2(float v, __nv_bfloat16& hi, __nv_bfloat16& lo) {
    hi = __float2bfloat16(v);
    lo = __float2bfloat16(v - __bfloat162float(hi));
}
__device__ __forceinline__ uint32_t smem_u32(const void* p) {
    uint32_t a;
    asm("{ .reg .u64 t; cvta.to.shared.u64 t, %1; cvt.u32.u64 %0, t; }" : "=r"(a) : "l"(p));
    return a;
}
__device__ __forceinline__ void cp16(uint32_t dst, const void* src, uint32_t srcsize) {
    asm volatile("cp.async.cg.shared.global [%0], [%1], 16, %2;"
                 :: "r"(dst), "l"(src), "r"(srcsize) : "memory");
}
#define CP_COMMIT() asm volatile("cp.async.commit_group;" ::: "memory")
#define CP_WAIT2()  asm volatile("cp.async.wait_group 2;" ::: "memory")

__device__ __forceinline__ void ldsm4(uint32_t* r, uint32_t addr) {
    asm volatile("ldmatrix.sync.aligned.m8n8.x4.shared.b16 {%0,%1,%2,%3}, [%4];"
                 : "=r"(r[0]), "=r"(r[1]), "=r"(r[2]), "=r"(r[3]) : "r"(addr));
}
__device__ __forceinline__ void mma16816(float* c, const uint32_t* a,
                                         uint32_t b0, uint32_t b1) {
    asm volatile(
        "mma.sync.aligned.m16n8k16.row.col.f32.bf16.bf16.f32 "
        "{%0,%1,%2,%3}, {%4,%5,%6,%7}, {%8,%9}, {%0,%1,%2,%3};"
        : "+f"(c[0]), "+f"(c[1]), "+f"(c[2]), "+f"(c[3])
        : "r"(a[0]), "r"(a[1]), "r"(a[2]), "r"(a[3]), "r"(b0), "r"(b1));
}

// ---------------- preprocessing kernels ----------------
__global__ void mean_kernel(const float* __restrict__ img) {
    int idx = blockIdx.x * blockDim.x + threadIdx.x;
    if (idx >= Bv * IMGv * IMGv) return;
    int b = idx / (IMGv * IMGv);
    int yx = idx % (IMGv * IMGv);
    const float* p = img + (size_t)b * Cv * IMGv * IMGv + yx;
    g_mean[idx] = (p[0] + p[IMGv * IMGv] + p[2 * IMGv * IMGv]) * (1.0f / 3.0f);
}

__global__ void patch_build_kernel(const float* __restrict__ img) {
    int idx = blockIdx.x * blockDim.x + threadIdx.x;
    if (idx >= MP * PDv) return;
    int pd = idx % PDv;
    int n  = (idx / PDv) % NPv;
    int b  = idx / (PDv * NPv);
    int c  = pd % 7;
    int pp = pd / 7;
    int px = pp % Pv, py = pp / Pv;
    int gy = n / Gv, gx = n % Gv;
    int y = gy * Pv + py, x = gx * Pv + px;
    float v;
    if (c < 3) {
        v = img[(((size_t)b * Cv + c) * IMGv + y) * IMGv + x];
    } else {
        int yy = y, xx = x;
        if      (c == 3) xx = x - Sv;
        else if (c == 4) xx = x + Sv;
        else if (c == 5) yy = y - Sv;
        else             yy = y + Sv;
        v = (xx < 0 || xx >= IMGv || yy < 0 || yy >= IMGv)
                ? 0.0f : g_mean[((size_t)b * IMGv + yy) * IMGv + xx];
    }
    __nv_bfloat16 hi, lo; split2(v, hi, lo);
    size_t row = (size_t)(b * NPv + n) * K3_PD;
    a2_patch[row + pd]            = hi;
    a2_patch[row + PDv + pd]      = lo;
    a2_patch[row + 2 * PDv + pd]  = hi;
}

__global__ void cls_init_kernel(const float* __restrict__ cls_tok,
                                const float* __restrict__ pos) {
    int d = threadIdx.x;
    int b = blockIdx.x;
    g_x[(size_t)b * Nv * DIMv + d] = cls_tok[d] + pos[d];
}

// weight convert: src [L][Nr,K] fp32 -> dst [L][Nr,3K] bf16  ([hi|hi|lo])
__global__ void convw_kernel(const float* __restrict__ src, __nv_bfloat16* __restrict__ dst,
                             int Nr, int K) {
    int idx = blockIdx.x * 256 + threadIdx.x;
    if (idx >= Nr * K) return;
    src += (size_t)blockIdx.y * Nr * K;
    dst += (size_t)blockIdx.y * Nr * 3 * K;
    int n = idx / K, k = idx % K;
    __nv_bfloat16 hi, lo; split2(src[idx], hi, lo);
    size_t r = (size_t)n * 3 * K;
    dst[r + k]         = hi;
    dst[r + K + k]     = hi;
    dst[r + 2 * K + k] = lo;
}

// ---------------- layernorm -> split-bf16 activation ([hi|lo|hi]) ----------------
__global__ void __launch_bounds__(128)
ln_split_kernel(const float* __restrict__ x, const float* __restrict__ g,
                const float* __restrict__ bta, __nv_bfloat16* __restrict__ out,
                long in_stride)
{
    long r = blockIdx.x;
    const float* xr = x + r * in_stride;
    int t = threadIdx.x;
    float v0 = xr[t], v1 = xr[t + 128], v2 = xr[t + 256];
    float s1 = v0 + v1 + v2;
    float s2 = v0 * v0 + v1 * v1 + v2 * v2;
    #pragma unroll
    for (int o = 16; o; o >>= 1) {
        s1 += __shfl_xor_sync(0xFFFFFFFFu, s1, o);
        s2 += __shfl_xor_sync(0xFFFFFFFFu, s2, o);
    }
    __shared__ float sh[8];
    int w = t >> 5;
    if ((t & 31) == 0) { sh[w] = s1; sh[4 + w] = s2; }
    __syncthreads();
    s1 = sh[0] + sh[1] + sh[2] + sh[3];
    s2 = sh[4] + sh[5] + sh[6] + sh[7];
    float mu  = s1 * (1.0f / DIMv);
    float var = s2 * (1.0f / DIMv) - mu * mu;
    float rs  = rsqrtf(var + EPSv);
    __nv_bfloat16* orow = out + r * (long)K3_DIM;
    #pragma unroll
    for (int q = 0; q < 3; q++) {
        int c = t + q * 128;
        float vv = (q == 0 ? v0 : (q == 1 ? v1 : v2));
        float y = (vv - mu) * rs * g[c] + bta[c];
        __nv_bfloat16 hi, lo; split2(y, hi, lo);
        orow[c]            = hi;
        orow[DIMv + c]     = lo;
        orow[2 * DIMv + c] = hi;
    }
}

// ---------------- attention: block per (b,h); writes split o ----------------
__global__ void __launch_bounds__(256)
attn2(const float* __restrict__ scale)
{
    __shared__ float Ks[Nv][DHv];
    __shared__ float Vs[Nv][DHv];
    int h = blockIdx.x % Hv;
    int b = blockIdx.x / Hv;
    const float* base = g_qkv + (size_t)b * Nv * (3 * INNERv) + h * DHv;

    for (int idx = threadIdx.x; idx < Nv * 8; idx += 256) {
        int r = idx >> 3;
        int c = (idx & 7) * 4;
        const float* row = base + (size_t)r * (3 * INNERv);
        *(float4*)&Ks[r][c] = *(const float4*)(row + INNERv + c);
        *(float4*)&Vs[r][c] = *(const float4*)(row + 2 * INNERv + c);
    }
    __syncthreads();

    int i = threadIdx.x;
    if (i >= Nv) return;
    float sc = scale[h];
    const float* qrow = base + (size_t)i * (3 * INNERv);
    float q[DHv];
    #pragma unroll
    for (int c = 0; c < DHv; c++) q[c] = qrow[c] * sc;

    float m = -INFINITY, s = 0.0f;
    float acc[DHv];
    #pragma unroll
    for (int c = 0; c < DHv; c++) acc[c] = 0.0f;

    for (int j = 0; j < Nv; j++) {
        if (j == i) continue;
        float d = 0.0f;
        #pragma unroll
        for (int c = 0; c < DHv; c++) d = fmaf(q[c], Ks[j][c], d);
        float nm = fmaxf(m, d);
        float f  = __expf(m - nm);
        float p  = __expf(d - nm);
        s = s * f + p;
        #pragma unroll
        for (int c = 0; c < DHv; c++) acc[c] = fmaf(acc[c], f, p * Vs[j][c]);
        m = nm;
    }
    float inv = 1.0f / s;
    __nv_bfloat16* o = a2_o + (size_t)(b * Nv + i) * K3_DIM + h * DHv;
    #pragma unroll
    for (int c = 0; c < DHv; c++) {
        __nv_bfloat16 hi, lo; split2(acc[c] * inv, hi, lo);
        o[c]            = hi;
        o[DIMv + c]     = lo;
        o[2 * DIMv + c] = hi;
    }
}

// ---------------- HMMA split-bf16 GEMM: C = A2[M,3K] * W2[N,3K]^T ----------------
// Persistent: grid = min(tiles, 296). CTA tile 128x128, 8 warps of 64x32, BK=32,
// 4-stage cp.async ring, single sync per chunk.
#define FLAG_GELU  1
#define FLAG_REMAP 2
#define FLAG_SPLIT 4
#define HSTRIDE 40                       // halves per smem row (80B, conflict-free)
#define HS_B    (128 * HSTRIDE * 2)      // 10240B
#define STAGEB  (2 * 128 * HSTRIDE * 2)  // 20480B
#define NSTAGE  4
#define SMEM_DYN (NSTAGE * STAGEB)       // 81920B

__device__ __forceinline__ void store_pair(
    float v0, float v1, int orow, int gn, int Nn,
    const float* bias, const float* resid, const float* pos,
    float* Cf, __nv_bfloat16* Cs, int flags)
{
    if (bias) { v0 += bias[gn]; v1 += bias[gn + 1]; }
    if (flags & FLAG_GELU) { v0 = gelu_exact(v0); v1 = gelu_exact(v1); }
    if (pos) {
        const float* pp = pos + (size_t)(orow % Nv) * Nn + gn;
        v0 += pp[0]; v1 += pp[1];
    }
    if (resid) {
        const float* rr = resid + (size_t)orow * Nn + gn;
        v0 += rr[0]; v1 += rr[1];
    }
    if (flags & FLAG_SPLIT) {
        __nv_bfloat16 h0, l0, h1, l1;
        split2(v0, h0, l0); split2(v1, h1, l1);
        __nv_bfloat16* p = Cs + (size_t)orow * 3 * Nn + gn;
        *(__nv_bfloat162*)(p)          = __halves2bfloat162(h0, h1);
        *(__nv_bfloat162*)(p + Nn)     = __halves2bfloat162(l0, l1);
        *(__nv_bfloat162*)(p + 2 * Nn) = __halves2bfloat162(h0, h1);
    } else {
        *(float2*)(Cf + (size_t)orow * Nn + gn) = make_float2(v0, v1);
    }
}

__global__ void __launch_bounds__(256, 2)
hm_gemm(const __nv_bfloat16* __restrict__ A, const __nv_bfloat16* __restrict__ W,
        const float* __restrict__ bias, const float* __restrict__ resid,
        const float* __restrict__ pos, float* __restrict__ Cf,
        __nv_bfloat16* __restrict__ Cs,
        int M, int Nn, int K3, int flags)
{
    extern __shared__ __align__(16) char sm[];
    uint32_t sbase = smem_u32(sm);
    int tid = threadIdx.x, lane = tid & 31, wid = tid >> 5;
    int wr = wid >> 2, wc = wid & 3;     // warp tile: 64(M) x 32(N)

    const int rbase = tid >> 2;          // 0..63
    const int kseg  = (tid & 3) * 8;     // halves
    const int nk = K3 / 32;
    const int tn = (Nn + 127) >> 7;
    const int tiles = ((M + 127) >> 7) * tn;

    for (int t = blockIdx.x; t < tiles; t += gridDim.x) {
        int m0 = (t / tn) * 128, n0 = (t % tn) * 128;

        float c[4][4][4];
        #pragma unroll
        for (int i = 0; i < 4; i++)
            #pragma unroll
            for (int j = 0; j < 4; j++)
                #pragma unroll
                for (int q = 0; q < 4; q++) c[i][j][q] = 0.0f;

        auto load_stage = [&](int slot, int ch) {
            uint32_t sa = sbase + slot * STAGEB;
            int kk = ch * 32;
            #pragma unroll
            for (int i = 0; i < 2; i++) {
                int r = rbase + i * 64;
                uint32_t dst = sa + (uint32_t)(r * HSTRIDE + kseg) * 2;
                const void* src = A + (size_t)(m0 + r) * K3 + kk + kseg;
                cp16(dst, src, (m0 + r < M) ? 16u : 0u);
            }
            #pragma unroll
            for (int i = 0; i < 2; i++) {
                int r = rbase + i * 64;
                uint32_t dst = sa + HS_B + (uint32_t)(r * HSTRIDE + kseg) * 2;
                const void* src = W + (size_t)(n0 + r) * K3 + kk + kseg;
                cp16(dst, src, (n0 + r < Nn) ? 16u : 0u);
            }
            CP_COMMIT();
        };

        #pragma unroll
        for (int s = 0; s < NSTAGE - 1; s++) load_stage(s, s);   // nk >= 3 always

        for (int ch = 0; ch < nk; ch++) {
            CP_WAIT2();
            __syncthreads();
            if (ch + NSTAGE - 1 < nk) load_stage((ch + NSTAGE - 1) & 3, ch + NSTAGE - 1);
            else CP_COMMIT();

            uint32_t sa = sbase + (ch & 3) * STAGEB;
            #pragma unroll
            for (int ko = 0; ko < 2; ko++) {
                int col = ko * 16 + ((lane >> 4) << 3);
                uint32_t a[4][4];
                #pragma unroll
                for (int mf = 0; mf < 4; mf++) {
                    int row = wr * 64 + mf * 16 + (lane & 15);
                    ldsm4(a[mf], sa + (uint32_t)(row * HSTRIDE + col) * 2);
                }
                uint32_t b[2][4];
                #pragma unroll
                for (int p = 0; p < 2; p++) {
                    int row = wc * 32 + p * 16 + (lane & 15);
                    ldsm4(b[p], sa + HS_B + (uint32_t)(row * HSTRIDE + col) * 2);
                }
                #pragma unroll
                for (int mf = 0; mf < 4; mf++)
                    #pragma unroll
                    for (int nf = 0; nf < 4; nf++) {
                        int p = nf >> 1, q = nf & 1;
                        mma16816(c[mf][nf], a[mf], b[p][q], b[p][2 + q]);
                    }
            }
        }

        // ---- epilogue ----
        #pragma unroll
        for (int mf = 0; mf < 4; mf++) {
            int r0 = m0 + wr * 64 + mf * 16 + (lane >> 2);
            #pragma unroll
            for (int nf = 0; nf < 4; nf++) {
                int gn = n0 + wc * 32 + nf * 8 + (lane & 3) * 2;
                if (gn >= Nn) continue;
                if (r0 < M) {
                    int orow = r0;
                    if (flags & FLAG_REMAP) { int b = r0 / NPv; orow = r0 + b + 1; }
                    store_pair(c[mf][nf][0], c[mf][nf][1], orow, gn, Nn,
                               bias, resid, pos, Cf, Cs, flags);
                }
                int r1 = r0 + 8;
                if (r1 < M) {
                    int orow = r1;
                    if (flags & FLAG_REMAP) { int b = r1 / NPv; orow = r1 + b + 1; }
                    store_pair(c[mf][nf][2], c[mf][nf][3], orow, gn, Nn,
                               bias, resid, pos, Cf, Cs, flags);
                }
            }
        }
        __syncthreads();   // stages may be reused by next tile
    }
}

// ---------------- host side ----------------
static inline void run_hm(const __nv_bfloat16* A, const __nv_bfloat16* W,
                          const float* bias, const float* resid, const float* pos,
                          float* Cf, __nv_bfloat16* Cs,
                          int M, int Nn, int K3, int flags)
{
    int tiles = ((M + 127) / 128) * ((Nn + 127) / 128);
    int grid = tiles < NPERSIST ? tiles : NPERSIST;
    hm_gemm<<<grid, 256, SMEM_DYN>>>(A, W, bias, resid, pos, Cf, Cs, M, Nn, K3, flags);
}

extern "C" void kernel_launch(void* const* d_in, const int* in_sizes, int n_in,
                              void* d_out, int out_size)
{
    const float* img     = (const float*)d_in[0];
    const float* patch_w = (const float*)d_in[1];
    const float* patch_b = (const float*)d_in[2];
    const float* pos_emb = (const float*)d_in[3];
    const float* cls_tok = (const float*)d_in[4];
    const float* ln1_g   = (const float*)d_in[5];
    const float* ln1_b   = (const float*)d_in[6];
    const float* qkv_w   = (const float*)d_in[7];
    const float* scale   = (const float*)d_in[8];
    const float* out_w   = (const float*)d_in[9];
    const float* out_b   = (const float*)d_in[10];
    const float* ln2_g   = (const float*)d_in[11];
    const float* ln2_b   = (const float*)d_in[12];
    const float* ff_w1   = (const float*)d_in[13];
    const float* ff_b1   = (const float*)d_in[14];
    const float* ff_w2   = (const float*)d_in[15];
    const float* ff_b2   = (const float*)d_in[16];
    const float* lnf_g   = (const float*)d_in[17];
    const float* lnf_b   = (const float*)d_in[18];
    const float* head_w  = (const float*)d_in[19];
    const float* head_b  = (const float*)d_in[20];

    cudaFuncSetAttribute(hm_gemm, cudaFuncAttributeMaxDynamicSharedMemorySize, SMEM_DYN);

    float *xp, *qkvp;
    __nv_bfloat16 *a2p, *a2hp, *a2op, *a2fp, *a2cp;
    __nv_bfloat16 *w2p, *w2q, *w2o, *w2f1, *w2f2, *w2h;
    cudaGetSymbolAddress((void**)&xp,   g_x);
    cudaGetSymbolAddress((void**)&qkvp, g_qkv);
    cudaGetSymbolAddress((void**)&a2p,  a2_patch);
    cudaGetSymbolAddress((void**)&a2hp, a2_h);
    cudaGetSymbolAddress((void**)&a2op, a2_o);
    cudaGetSymbolAddress((void**)&a2fp, a2_ff);
    cudaGetSymbolAddress((void**)&a2cp, a2_cls);
    cudaGetSymbolAddress((void**)&w2p,  w2_patch);
    cudaGetSymbolAddress((void**)&w2q,  w2_qkv);
    cudaGetSymbolAddress((void**)&w2o,  w2_out);
    cudaGetSymbolAddress((void**)&w2f1, w2_ff1);
    cudaGetSymbolAddress((void**)&w2f2, w2_ff2);
    cudaGetSymbolAddress((void**)&w2h,  w2_head);

    // Launch order: my #4 (= global #6 after 2 harness launches) is the patch
    // hm_gemm so ncu finally profiles the GEMM.
    {
        int n = Bv * IMGv * IMGv;
        mean_kernel<<<(n + 255) / 256, 256>>>(img);                               // 1
        int np = MP * PDv;
        patch_build_kernel<<<(np + 255) / 256, 256>>>(img);                       // 2
        int nw = DIMv * PDv;
        convw_kernel<<<dim3((nw + 255) / 256, 1), 256>>>(patch_w, w2p, DIMv, PDv);// 3
    }
    run_hm(a2p, w2p, patch_b, nullptr, pos_emb, xp, nullptr,
           MP, DIMv, K3_PD, FLAG_REMAP);                                          // 4 <- profiled
    cls_init_kernel<<<Bv, DIMv>>>(cls_tok, pos_emb);                              // 5

    {
        int n;
        n = 3 * INNERv * DIMv;
        convw_kernel<<<dim3((n + 255) / 256, DEPTHv), 256>>>(qkv_w, w2q, 3 * INNERv, DIMv);
        n = DIMv * INNERv;
        convw_kernel<<<dim3((n + 255) / 256, DEPTHv), 256>>>(out_w, w2o, DIMv, INNERv);
        n = MLPv * DIMv;
        convw_kernel<<<dim3((n + 255) / 256, DEPTHv), 256>>>(ff_w1, w2f1, MLPv, DIMv);
        n = DIMv * MLPv;
        convw_kernel<<<dim3((n + 255) / 256, DEPTHv), 256>>>(ff_w2, w2f2, DIMv, MLPv);
        n = NCLSv * DIMv;
        convw_kernel<<<dim3((n + 255) / 256, 1), 256>>>(head_w, w2h, NCLSv, DIMv);
    }

    for (int L = 0; L < DEPTHv; L++) {
        ln_split_kernel<<<TOK, 128>>>(xp, ln1_g + L * DIMv, ln1_b + L * DIMv, a2hp, DIMv);
        run_hm(a2hp, w2q + (size_t)L * 3 * INNERv * K3_DIM, nullptr, nullptr, nullptr,
               qkvp, nullptr, TOK, 3 * INNERv, K3_DIM, 0);
        attn2<<<Bv * Hv, 256>>>(scale + L * Hv);
        run_hm(a2op, w2o + (size_t)L * DIMv * K3_DIM, out_b + L * DIMv, xp, nullptr,
               xp, nullptr, TOK, DIMv, K3_DIM, 0);
        ln_split_kernel<<<TOK, 128>>>(xp, ln2_g + L * DIMv, ln2_b + L * DIMv, a2hp, DIMv);
        run_hm(a2hp, w2f1 + (size_t)L * MLPv * K3_DIM, ff_b1 + L * MLPv, nullptr, nullptr,
               nullptr, a2fp, TOK, MLPv, K3_DIM, FLAG_GELU | FLAG_SPLIT);
        run_hm(a2fp, w2f2 + (size_t)L * DIMv * K3_MLP, ff_b2 + L * DIMv, xp, nullptr,
               xp, nullptr, TOK, DIMv, K3_MLP, 0);
    }

    // final LN on cls rows (row b = x[b*197*384]) -> split, then head
    ln_split_kernel<<<Bv, 128>>>(xp, lnf_g, lnf_b, a2cp, (long)Nv * DIMv);
    run_hm(a2cp, w2h, head_b, nullptr, nullptr, (float*)d_out, nullptr,
           Bv, NCLSv, K3_DIM, 0);
}

// round 11
// speedup vs baseline: 1.4943x; 1.4700x over previous
#include <cuda_runtime.h>
#include <cuda_bf16.h>
#include <cuda_fp16.h>
#include <cstdint>
#include <cmath>

// ---------------- problem constants ----------------
#define Bv     64
#define Cv     3
#define IMGv   224
#define Pv     16
#define Sv     8
#define Gv     14
#define NPv    196
#define Nv     197
#define DIMv   384
#define DEPTHv 12
#define Hv     12
#define DHv    32
#define INNERv 384
#define MLPv   1536
#define NCLSv  1000
#define PDv    1792
#define TOK    (Bv*Nv)      // 12608
#define MP     (Bv*NPv)     // 12544
#define EPSv   1e-5f

#define K2_DIM (2*DIMv)     // 768
#define K2_MLP (2*MLPv)     // 3072
#define K2_PD  (2*PDv)      // 3584

// ---------------- scratch (device globals; no allocation allowed) ----------------
__device__ float g_mean [Bv * IMGv * IMGv];
__device__ float g_x    [TOK * DIMv];
__device__ float g_qkv  [TOK * 3 * INNERv];

__device__ __half a2_patch[(size_t)MP  * K2_PD];
__device__ __half a2_h    [(size_t)TOK * K2_DIM];
__device__ __half a2_o    [(size_t)TOK * K2_DIM];
__device__ __half a2_ff   [(size_t)TOK * K2_MLP];
__device__ __half a2_cls  [Bv * K2_DIM];

__device__ __half w2_patch[(size_t)DIMv  * K2_PD];
__device__ __half w2_qkv  [(size_t)DEPTHv * 3*INNERv * K2_DIM];
__device__ __half w2_out  [(size_t)DEPTHv * DIMv     * K2_DIM];
__device__ __half w2_ff1  [(size_t)DEPTHv * MLPv     * K2_DIM];
__device__ __half w2_ff2  [(size_t)DEPTHv * DIMv     * K2_MLP];
__device__ __half w2_head [(size_t)NCLSv * K2_DIM];

// ---------------- small helpers ----------------
__device__ __forceinline__ float gelu_exact(float x) {
    return 0.5f * x * (1.0f + erff(x * 0.70710678118654752440f));
}
__device__ __forceinline__ void split2h(float v, __half& hi, __half& lo) {
    hi = __float2half(v);
    lo = __float2half(v - __half2float(hi));
}
__device__ __forceinline__ uint32_t smem_u32(const void* p) {
    uint32_t a;
    asm("{ .reg .u64 t; cvta.to.shared.u64 t, %1; cvt.u32.u64 %0, t; }" : "=r"(a) : "l"(p));
    return a;
}
__device__ __forceinline__ void cp16(uint32_t dst, const void* src, uint32_t srcsize) {
    asm volatile("cp.async.cg.shared.global [%0], [%1], 16, %2;"
                 :: "r"(dst), "l"(src), "r"(srcsize) : "memory");
}
#define CP_COMMIT() asm volatile("cp.async.commit_group;" ::: "memory")
#define CP_WAIT2()  asm volatile("cp.async.wait_group 2;" ::: "memory")

__device__ __forceinline__ void ldsm4(uint32_t* r, uint32_t addr) {
    asm volatile("ldmatrix.sync.aligned.m8n8.x4.shared.b16 {%0,%1,%2,%3}, [%4];"
                 : "=r"(r[0]), "=r"(r[1]), "=r"(r[2]), "=r"(r[3]) : "r"(addr));
}
__device__ __forceinline__ void mma16816(float* c, const uint32_t* a,
                                         uint32_t b0, uint32_t b1) {
    asm volatile(
        "mma.sync.aligned.m16n8k16.row.col.f32.f16.f16.f32 "
        "{%0,%1,%2,%3}, {%4,%5,%6,%7}, {%8,%9}, {%0,%1,%2,%3};"
        : "+f"(c[0]), "+f"(c[1]), "+f"(c[2]), "+f"(c[3])
        : "r"(a[0]), "r"(a[1]), "r"(a[2]), "r"(a[3]), "r"(b0), "r"(b1));
}

// ---------------- preprocessing kernels ----------------
__global__ void mean_kernel(const float* __restrict__ img) {
    int idx = blockIdx.x * blockDim.x + threadIdx.x;
    if (idx >= Bv * IMGv * IMGv) return;
    int b = idx / (IMGv * IMGv);
    int yx = idx % (IMGv * IMGv);
    const float* p = img + (size_t)b * Cv * IMGv * IMGv + yx;
    g_mean[idx] = (p[0] + p[IMGv * IMGv] + p[2 * IMGv * IMGv]) * (1.0f / 3.0f);
}

__global__ void patch_build_kernel(const float* __restrict__ img) {
    int idx = blockIdx.x * blockDim.x + threadIdx.x;
    if (idx >= MP * PDv) return;
    int pd = idx % PDv;
    int n  = (idx / PDv) % NPv;
    int b  = idx / (PDv * NPv);
    int c  = pd % 7;
    int pp = pd / 7;
    int px = pp % Pv, py = pp / Pv;
    int gy = n / Gv, gx = n % Gv;
    int y = gy * Pv + py, x = gx * Pv + px;
    float v;
    if (c < 3) {
        v = img[(((size_t)b * Cv + c) * IMGv + y) * IMGv + x];
    } else {
        int yy = y, xx = x;
        if      (c == 3) xx = x - Sv;
        else if (c == 4) xx = x + Sv;
        else if (c == 5) yy = y - Sv;
        else             yy = y + Sv;
        v = (xx < 0 || xx >= IMGv || yy < 0 || yy >= IMGv)
                ? 0.0f : g_mean[((size_t)b * IMGv + yy) * IMGv + xx];
    }
    __half hi, lo; split2h(v, hi, lo);
    size_t row = (size_t)(b * NPv + n) * K2_PD;
    a2_patch[row + pd]       = hi;
    a2_patch[row + PDv + pd] = lo;
}

__global__ void cls_init_kernel(const float* __restrict__ cls_tok,
                                const float* __restrict__ pos) {
    int d = threadIdx.x;
    int b = blockIdx.x;
    g_x[(size_t)b * Nv * DIMv + d] = cls_tok[d] + pos[d];
}

// weight convert: src [L][Nr,K] fp32 -> dst [L][Nr,2K] fp16  ([hi|hi])
__global__ void convw_kernel(const float* __restrict__ src, __half* __restrict__ dst,
                             int Nr, int K) {
    int idx = blockIdx.x * 256 + threadIdx.x;
    if (idx >= Nr * K) return;
    src += (size_t)blockIdx.y * Nr * K;
    dst += (size_t)blockIdx.y * Nr * 2 * K;
    int n = idx / K, k = idx % K;
    __half hi = __float2half(src[idx]);
    size_t r = (size_t)n * 2 * K;
    dst[r + k]     = hi;
    dst[r + K + k] = hi;
}

// ---------------- layernorm -> split-fp16 activation ([hi|lo]) ----------------
__global__ void __launch_bounds__(128)
ln_split_kernel(const float* __restrict__ x, const float* __restrict__ g,
                const float* __restrict__ bta, __half* __restrict__ out,
                long in_stride)
{
    long r = blockIdx.x;
    const float* xr = x + r * in_stride;
    int t = threadIdx.x;
    float v0 = xr[t], v1 = xr[t + 128], v2 = xr[t + 256];
    float s1 = v0 + v1 + v2;
    float s2 = v0 * v0 + v1 * v1 + v2 * v2;
    #pragma unroll
    for (int o = 16; o; o >>= 1) {
        s1 += __shfl_xor_sync(0xFFFFFFFFu, s1, o);
        s2 += __shfl_xor_sync(0xFFFFFFFFu, s2, o);
    }
    __shared__ float sh[8];
    int w = t >> 5;
    if ((t & 31) == 0) { sh[w] = s1; sh[4 + w] = s2; }
    __syncthreads();
    s1 = sh[0] + sh[1] + sh[2] + sh[3];
    s2 = sh[4] + sh[5] + sh[6] + sh[7];
    float mu  = s1 * (1.0f / DIMv);
    float var = s2 * (1.0f / DIMv) - mu * mu;
    float rs  = rsqrtf(var + EPSv);
    __half* orow = out + r * (long)K2_DIM;
    #pragma unroll
    for (int q = 0; q < 3; q++) {
        int c = t + q * 128;
        float vv = (q == 0 ? v0 : (q == 1 ? v1 : v2));
        float y = (vv - mu) * rs * g[c] + bta[c];
        __half hi, lo; split2h(y, hi, lo);
        orow[c]        = hi;
        orow[DIMv + c] = lo;
    }
}

// ---------------- attention: block per (b,h); writes split o ----------------
__global__ void __launch_bounds__(256)
attn2(const float* __restrict__ scale)
{
    __shared__ float Ks[Nv][DHv];
    __shared__ float Vs[Nv][DHv];
    int h = blockIdx.x % Hv;
    int b = blockIdx.x / Hv;
    const float* base = g_qkv + (size_t)b * Nv * (3 * INNERv) + h * DHv;

    for (int idx = threadIdx.x; idx < Nv * 8; idx += 256) {
        int r = idx >> 3;
        int c = (idx & 7) * 4;
        const float* row = base + (size_t)r * (3 * INNERv);
        *(float4*)&Ks[r][c] = *(const float4*)(row + INNERv + c);
        *(float4*)&Vs[r][c] = *(const float4*)(row + 2 * INNERv + c);
    }
    __syncthreads();

    int i = threadIdx.x;
    if (i >= Nv) return;
    float sc = scale[h];
    const float* qrow = base + (size_t)i * (3 * INNERv);
    float q[DHv];
    #pragma unroll
    for (int c = 0; c < DHv; c++) q[c] = qrow[c] * sc;

    float m = -INFINITY, s = 0.0f;
    float acc[DHv];
    #pragma unroll
    for (int c = 0; c < DHv; c++) acc[c] = 0.0f;

    for (int j = 0; j < Nv; j++) {
        if (j == i) continue;
        float d = 0.0f;
        #pragma unroll
        for (int c = 0; c < DHv; c++) d = fmaf(q[c], Ks[j][c], d);
        float nm = fmaxf(m, d);
        float f  = __expf(m - nm);
        float p  = __expf(d - nm);
        s = s * f + p;
        #pragma unroll
        for (int c = 0; c < DHv; c++) acc[c] = fmaf(acc[c], f, p * Vs[j][c]);
        m = nm;
    }
    float inv = 1.0f / s;
    __half* o = a2_o + (size_t)(b * Nv + i) * K2_DIM + h * DHv;
    #pragma unroll
    for (int c = 0; c < DHv; c++) {
        __half hi, lo; split2h(acc[c] * inv, hi, lo);
        o[c]        = hi;
        o[DIMv + c] = lo;
    }
}

// ---------------- HMMA split-fp16 GEMM: C = A2[M,2K] * W2[N,2K]^T ----------------
// CTA tile 128x128, 8 warps of 64x32, BK=32, 4-stage cp.async ring, single sync.
#define FLAG_GELU  1
#define FLAG_REMAP 2
#define FLAG_SPLIT 4
#define HSTRIDE 40                       // halves per smem row (80B, conflict-free)
#define HS_B    (128 * HSTRIDE * 2)      // 10240B
#define STAGEB  (2 * 128 * HSTRIDE * 2)  // 20480B
#define NSTAGE  4
#define SMEM_DYN (NSTAGE * STAGEB)       // 81920B

__device__ __forceinline__ void store_pair(
    float v0, float v1, int orow, int gn, int Nn,
    const float* bias, const float* resid, const float* pos,
    float* Cf, __half* Cs, int flags)
{
    if (bias) { v0 += bias[gn]; v1 += bias[gn + 1]; }
    if (flags & FLAG_GELU) { v0 = gelu_exact(v0); v1 = gelu_exact(v1); }
    if (pos) {
        const float* pp = pos + (size_t)(orow % Nv) * Nn + gn;
        v0 += pp[0]; v1 += pp[1];
    }
    if (resid) {
        const float* rr = resid + (size_t)orow * Nn + gn;
        v0 += rr[0]; v1 += rr[1];
    }
    if (flags & FLAG_SPLIT) {
        __half h0, l0, h1, l1;
        split2h(v0, h0, l0); split2h(v1, h1, l1);
        __half* p = Cs + (size_t)orow * 2 * Nn + gn;
        *(__half2*)(p)      = __halves2half2(h0, h1);
        *(__half2*)(p + Nn) = __halves2half2(l0, l1);
    } else {
        *(float2*)(Cf + (size_t)orow * Nn + gn) = make_float2(v0, v1);
    }
}

__global__ void __launch_bounds__(256, 2)
hm_gemm(const __half* __restrict__ A, const __half* __restrict__ W,
        const float* __restrict__ bias, const float* __restrict__ resid,
        const float* __restrict__ pos, float* __restrict__ Cf,
        __half* __restrict__ Cs,
        int M, int Nn, int K2, int flags)
{
    extern __shared__ __align__(16) char sm[];
    uint32_t sbase = smem_u32(sm);
    int tid = threadIdx.x, lane = tid & 31, wid = tid >> 5;
    int m0 = blockIdx.y * 128, n0 = blockIdx.x * 128;
    int wr = wid >> 2, wc = wid & 3;     // warp tile: 64(M) x 32(N)

    float c[4][4][4];
    #pragma unroll
    for (int i = 0; i < 4; i++)
        #pragma unroll
        for (int j = 0; j < 4; j++)
            #pragma unroll
            for (int q = 0; q < 4; q++) c[i][j][q] = 0.0f;

    const int rbase = tid >> 2;          // 0..63
    const int kseg  = (tid & 3) * 8;     // halves

    const int nk = K2 / 32;

    auto load_stage = [&](int slot, int ch) {
        uint32_t sa = sbase + slot * STAGEB;
        int kk = ch * 32;
        #pragma unroll
        for (int i = 0; i < 2; i++) {
            int r = rbase + i * 64;
            uint32_t dst = sa + (uint32_t)(r * HSTRIDE + kseg) * 2;
            const void* src = A + (size_t)(m0 + r) * K2 + kk + kseg;
            cp16(dst, src, (m0 + r < M) ? 16u : 0u);
        }
        #pragma unroll
        for (int i = 0; i < 2; i++) {
            int r = rbase + i * 64;
            uint32_t dst = sa + HS_B + (uint32_t)(r * HSTRIDE + kseg) * 2;
            const void* src = W + (size_t)(n0 + r) * K2 + kk + kseg;
            cp16(dst, src, (n0 + r < Nn) ? 16u : 0u);
        }
        CP_COMMIT();
    };

    #pragma unroll
    for (int s = 0; s < NSTAGE - 1; s++) load_stage(s, s);   // nk >= 3 always

    for (int ch = 0; ch < nk; ch++) {
        CP_WAIT2();
        __syncthreads();
        if (ch + NSTAGE - 1 < nk) load_stage((ch + NSTAGE - 1) & 3, ch + NSTAGE - 1);
        else CP_COMMIT();

        uint32_t sa = sbase + (ch & 3) * STAGEB;
        #pragma unroll
        for (int ko = 0; ko < 2; ko++) {
            int col = ko * 16 + ((lane >> 4) << 3);
            uint32_t a[4][4];
            #pragma unroll
            for (int mf = 0; mf < 4; mf++) {
                int row = wr * 64 + mf * 16 + (lane & 15);
                ldsm4(a[mf], sa + (uint32_t)(row * HSTRIDE + col) * 2);
            }
            uint32_t b[2][4];
            #pragma unroll
            for (int p = 0; p < 2; p++) {
                int row = wc * 32 + p * 16 + (lane & 15);
                ldsm4(b[p], sa + HS_B + (uint32_t)(row * HSTRIDE + col) * 2);
            }
            #pragma unroll
            for (int mf = 0; mf < 4; mf++)
                #pragma unroll
                for (int nf = 0; nf < 4; nf++) {
                    int p = nf >> 1, q = nf & 1;
                    mma16816(c[mf][nf], a[mf], b[p][q], b[p][2 + q]);
                }
        }
    }

    // ---- epilogue ----
    #pragma unroll
    for (int mf = 0; mf < 4; mf++) {
        int r0 = m0 + wr * 64 + mf * 16 + (lane >> 2);
        #pragma unroll
        for (int nf = 0; nf < 4; nf++) {
            int gn = n0 + wc * 32 + nf * 8 + (lane & 3) * 2;
            if (gn >= Nn) continue;
            if (r0 < M) {
                int orow = r0;
                if (flags & FLAG_REMAP) { int b = r0 / NPv; orow = r0 + b + 1; }
                store_pair(c[mf][nf][0], c[mf][nf][1], orow, gn, Nn,
                           bias, resid, pos, Cf, Cs, flags);
            }
            int r1 = r0 + 8;
            if (r1 < M) {
                int orow = r1;
                if (flags & FLAG_REMAP) { int b = r1 / NPv; orow = r1 + b + 1; }
                store_pair(c[mf][nf][2], c[mf][nf][3], orow, gn, Nn,
                           bias, resid, pos, Cf, Cs, flags);
            }
        }
    }
}

// ---------------- host side ----------------
static inline void run_hm(const __half* A, const __half* W,
                          const float* bias, const float* resid, const float* pos,
                          float* Cf, __half* Cs,
                          int M, int Nn, int K2, int flags)
{
    dim3 grid((Nn + 127) / 128, (M + 127) / 128);
    hm_gemm<<<grid, 256, SMEM_DYN>>>(A, W, bias, resid, pos, Cf, Cs, M, Nn, K2, flags);
}

extern "C" void kernel_launch(void* const* d_in, const int* in_sizes, int n_in,
                              void* d_out, int out_size)
{
    const float* img     = (const float*)d_in[0];
    const float* patch_w = (const float*)d_in[1];
    const float* patch_b = (const float*)d_in[2];
    const float* pos_emb = (const float*)d_in[3];
    const float* cls_tok = (const float*)d_in[4];
    const float* ln1_g   = (const float*)d_in[5];
    const float* ln1_b   = (const float*)d_in[6];
    const float* qkv_w   = (const float*)d_in[7];
    const float* scale   = (const float*)d_in[8];
    const float* out_w   = (const float*)d_in[9];
    const float* out_b   = (const float*)d_in[10];
    const float* ln2_g   = (const float*)d_in[11];
    const float* ln2_b   = (const float*)d_in[12];
    const float* ff_w1   = (const float*)d_in[13];
    const float* ff_b1   = (const float*)d_in[14];
    const float* ff_w2   = (const float*)d_in[15];
    const float* ff_b2   = (const float*)d_in[16];
    const float* lnf_g   = (const float*)d_in[17];
    const float* lnf_b   = (const float*)d_in[18];
    const float* head_w  = (const float*)d_in[19];
    const float* head_b  = (const float*)d_in[20];

    cudaFuncSetAttribute(hm_gemm, cudaFuncAttributeMaxDynamicSharedMemorySize, SMEM_DYN);

    float *xp, *qkvp;
    __half *a2p, *a2hp, *a2op, *a2fp, *a2cp;
    __half *w2p, *w2q, *w2o, *w2f1, *w2f2, *w2h;
    cudaGetSymbolAddress((void**)&xp,   g_x);
    cudaGetSymbolAddress((void**)&qkvp, g_qkv);
    cudaGetSymbolAddress((void**)&a2p,  a2_patch);
    cudaGetSymbolAddress((void**)&a2hp, a2_h);
    cudaGetSymbolAddress((void**)&a2op, a2_o);
    cudaGetSymbolAddress((void**)&a2fp, a2_ff);
    cudaGetSymbolAddress((void**)&a2cp, a2_cls);
    cudaGetSymbolAddress((void**)&w2p,  w2_patch);
    cudaGetSymbolAddress((void**)&w2q,  w2_qkv);
    cudaGetSymbolAddress((void**)&w2o,  w2_out);
    cudaGetSymbolAddress((void**)&w2f1, w2_ff1);
    cudaGetSymbolAddress((void**)&w2f2, w2_ff2);
    cudaGetSymbolAddress((void**)&w2h,  w2_head);

    // Launch order: my #4 (= global #6 after harness launches) is the patch
    // hm_gemm so ncu profiles the GEMM.
    {
        int n = Bv * IMGv * IMGv;
        mean_kernel<<<(n + 255) / 256, 256>>>(img);                               // 1
        int np = MP * PDv;
        patch_build_kernel<<<(np + 255) / 256, 256>>>(img);                       // 2
        int nw = DIMv * PDv;
        convw_kernel<<<dim3((nw + 255) / 256, 1), 256>>>(patch_w, w2p, DIMv, PDv);// 3
    }
    run_hm(a2p, w2p, patch_b, nullptr, pos_emb, xp, nullptr,
           MP, DIMv, K2_PD, FLAG_REMAP);                                          // 4 <- profiled
    cls_init_kernel<<<Bv, DIMv>>>(cls_tok, pos_emb);                              // 5

    {
        int n;
        n = 3 * INNERv * DIMv;
        convw_kernel<<<dim3((n + 255) / 256, DEPTHv), 256>>>(qkv_w, w2q, 3 * INNERv, DIMv);
        n = DIMv * INNERv;
        convw_kernel<<<dim3((n + 255) / 256, DEPTHv), 256>>>(out_w, w2o, DIMv, INNERv);
        n = MLPv * DIMv;
        convw_kernel<<<dim3((n + 255) / 256, DEPTHv), 256>>>(ff_w1, w2f1, MLPv, DIMv);
        n = DIMv * MLPv;
        convw_kernel<<<dim3((n + 255) / 256, DEPTHv), 256>>>(ff_w2, w2f2, DIMv, MLPv);
        n = NCLSv * DIMv;
        convw_kernel<<<dim3((n + 255) / 256, 1), 256>>>(head_w, w2h, NCLSv, DIMv);
    }

    for (int L = 0; L < DEPTHv; L++) {
        ln_split_kernel<<<TOK, 128>>>(xp, ln1_g + L * DIMv, ln1_b + L * DIMv, a2hp, DIMv);
        run_hm(a2hp, w2q + (size_t)L * 3 * INNERv * K2_DIM, nullptr, nullptr, nullptr,
               qkvp, nullptr, TOK, 3 * INNERv, K2_DIM, 0);
        attn2<<<Bv * Hv, 256>>>(scale + L * Hv);
        run_hm(a2op, w2o + (size_t)L * DIMv * K2_DIM, out_b + L * DIMv, xp, nullptr,
               xp, nullptr, TOK, DIMv, K2_DIM, 0);
        ln_split_kernel<<<TOK, 128>>>(xp, ln2_g + L * DIMv, ln2_b + L * DIMv, a2hp, DIMv);
        run_hm(a2hp, w2f1 + (size_t)L * MLPv * K2_DIM, ff_b1 + L * MLPv, nullptr, nullptr,
               nullptr, a2fp, TOK, MLPv, K2_DIM, FLAG_GELU | FLAG_SPLIT);
        run_hm(a2fp, w2f2 + (size_t)L * DIMv * K2_MLP, ff_b2 + L * DIMv, xp, nullptr,
               xp, nullptr, TOK, DIMv, K2_MLP, 0);
    }

    // final LN on cls rows (row b = x[b*197*384]) -> split, then head
    ln_split_kernel<<<Bv, 128>>>(xp, lnf_g, lnf_b, a2cp, (long)Nv * DIMv);
    run_hm(a2cp, w2h, head_b, nullptr, nullptr, (float*)d_out, nullptr,
           Bv, NCLSv, K2_DIM, 0);
}

// round 12
// speedup vs baseline: 1.5693x; 1.0502x over previous
#include <cuda_runtime.h>
#include <cuda_bf16.h>
#include <cuda_fp16.h>
#include <cstdint>
#include <cmath>

// ---------------- problem constants ----------------
#define Bv     64
#define Cv     3
#define IMGv   224
#define Pv     16
#define Sv     8
#define Gv     14
#define NPv    196
#define Nv     197
#define DIMv   384
#define DEPTHv 12
#define Hv     12
#define DHv    32
#define INNERv 384
#define MLPv   1536
#define NCLSv  1000
#define PDv    1792
#define TOK    (Bv*Nv)      // 12608
#define MP     (Bv*NPv)     // 12544
#define EPSv   1e-5f

#define K2_DIM (2*DIMv)     // 768
#define K2_MLP (2*MLPv)     // 3072
#define K2_PD  (2*PDv)      // 3584

// ---------------- scratch (device globals; no allocation allowed) ----------------
__device__ float g_mean [Bv * IMGv * IMGv];
__device__ float g_x    [TOK * DIMv];
__device__ float g_qkv  [TOK * 3 * INNERv];

__device__ __half a2_patch[(size_t)MP  * K2_PD];
__device__ __half a2_h    [(size_t)TOK * K2_DIM];
__device__ __half a2_o    [(size_t)TOK * K2_DIM];
__device__ __half a2_ff   [(size_t)TOK * K2_MLP];
__device__ __half a2_cls  [Bv * K2_DIM];

__device__ __half w2_patch[(size_t)DIMv  * K2_PD];
__device__ __half w2_qkv  [(size_t)DEPTHv * 3*INNERv * K2_DIM];
__device__ __half w2_out  [(size_t)DEPTHv * DIMv     * K2_DIM];
__device__ __half w2_ff1  [(size_t)DEPTHv * MLPv     * K2_DIM];
__device__ __half w2_ff2  [(size_t)DEPTHv * DIMv     * K2_MLP];
__device__ __half w2_head [(size_t)NCLSv * K2_DIM];

// ---------------- small helpers ----------------
__device__ __forceinline__ float gelu_exact(float x) {
    return 0.5f * x * (1.0f + erff(x * 0.70710678118654752440f));
}
__device__ __forceinline__ void split2h(float v, __half& hi, __half& lo) {
    hi = __float2half(v);
    lo = __float2half(v - __half2float(hi));
}
__device__ __forceinline__ uint32_t smem_u32(const void* p) {
    uint32_t a;
    asm("{ .reg .u64 t; cvta.to.shared.u64 t, %1; cvt.u32.u64 %0, t; }" : "=r"(a) : "l"(p));
    return a;
}
__device__ __forceinline__ void cp16(uint32_t dst, const void* src, uint32_t srcsize) {
    asm volatile("cp.async.cg.shared.global [%0], [%1], 16, %2;"
                 :: "r"(dst), "l"(src), "r"(srcsize) : "memory");
}
#define CP_COMMIT() asm volatile("cp.async.commit_group;" ::: "memory")
#define CP_WAIT2()  asm volatile("cp.async.wait_group 2;" ::: "memory")

__device__ __forceinline__ void ldsm4(uint32_t* r, uint32_t addr) {
    asm volatile("ldmatrix.sync.aligned.m8n8.x4.shared.b16 {%0,%1,%2,%3}, [%4];"
                 : "=r"(r[0]), "=r"(r[1]), "=r"(r[2]), "=r"(r[3]) : "r"(addr));
}
__device__ __forceinline__ void mma16816(float* c, const uint32_t* a,
                                         uint32_t b0, uint32_t b1) {
    asm volatile(
        "mma.sync.aligned.m16n8k16.row.col.f32.f16.f16.f32 "
        "{%0,%1,%2,%3}, {%4,%5,%6,%7}, {%8,%9}, {%0,%1,%2,%3};"
        : "+f"(c[0]), "+f"(c[1]), "+f"(c[2]), "+f"(c[3])
        : "r"(a[0]), "r"(a[1]), "r"(a[2]), "r"(a[3]), "r"(b0), "r"(b1));
}

// ---------------- preprocessing kernels ----------------
__global__ void mean_kernel(const float* __restrict__ img) {
    int idx = blockIdx.x * blockDim.x + threadIdx.x;
    if (idx >= Bv * IMGv * IMGv) return;
    int b = idx / (IMGv * IMGv);
    int yx = idx % (IMGv * IMGv);
    const float* p = img + (size_t)b * Cv * IMGv * IMGv + yx;
    g_mean[idx] = (p[0] + p[IMGv * IMGv] + p[2 * IMGv * IMGv]) * (1.0f / 3.0f);
}

__global__ void patch_build_kernel(const float* __restrict__ img) {
    int idx = blockIdx.x * blockDim.x + threadIdx.x;
    if (idx >= MP * PDv) return;
    int pd = idx % PDv;
    int n  = (idx / PDv) % NPv;
    int b  = idx / (PDv * NPv);
    int c  = pd % 7;
    int pp = pd / 7;
    int px = pp % Pv, py = pp / Pv;
    int gy = n / Gv, gx = n % Gv;
    int y = gy * Pv + py, x = gx * Pv + px;
    float v;
    if (c < 3) {
        v = img[(((size_t)b * Cv + c) * IMGv + y) * IMGv + x];
    } else {
        int yy = y, xx = x;
        if      (c == 3) xx = x - Sv;
        else if (c == 4) xx = x + Sv;
        else if (c == 5) yy = y - Sv;
        else             yy = y + Sv;
        v = (xx < 0 || xx >= IMGv || yy < 0 || yy >= IMGv)
                ? 0.0f : g_mean[((size_t)b * IMGv + yy) * IMGv + xx];
    }
    __half hi, lo; split2h(v, hi, lo);
    size_t row = (size_t)(b * NPv + n) * K2_PD;
    a2_patch[row + pd]       = hi;
    a2_patch[row + PDv + pd] = lo;
}

__global__ void cls_init_kernel(const float* __restrict__ cls_tok,
                                const float* __restrict__ pos) {
    int d = threadIdx.x;
    int b = blockIdx.x;
    g_x[(size_t)b * Nv * DIMv + d] = cls_tok[d] + pos[d];
}

// weight convert: src [L][Nr,K] fp32 -> dst [L][Nr,2K] fp16  ([hi|hi])
__global__ void convw_kernel(const float* __restrict__ src, __half* __restrict__ dst,
                             int Nr, int K) {
    int idx = blockIdx.x * 256 + threadIdx.x;
    if (idx >= Nr * K) return;
    src += (size_t)blockIdx.y * Nr * K;
    dst += (size_t)blockIdx.y * Nr * 2 * K;
    int n = idx / K, k = idx % K;
    __half hi = __float2half(src[idx]);
    size_t r = (size_t)n * 2 * K;
    dst[r + k]     = hi;
    dst[r + K + k] = hi;
}

// ---------------- layernorm -> split-fp16 activation ([hi|lo]) ----------------
__global__ void __launch_bounds__(128)
ln_split_kernel(const float* __restrict__ x, const float* __restrict__ g,
                const float* __restrict__ bta, __half* __restrict__ out,
                long in_stride)
{
    long r = blockIdx.x;
    const float* xr = x + r * in_stride;
    int t = threadIdx.x;
    float v0 = xr[t], v1 = xr[t + 128], v2 = xr[t + 256];
    float s1 = v0 + v1 + v2;
    float s2 = v0 * v0 + v1 * v1 + v2 * v2;
    #pragma unroll
    for (int o = 16; o; o >>= 1) {
        s1 += __shfl_xor_sync(0xFFFFFFFFu, s1, o);
        s2 += __shfl_xor_sync(0xFFFFFFFFu, s2, o);
    }
    __shared__ float sh[8];
    int w = t >> 5;
    if ((t & 31) == 0) { sh[w] = s1; sh[4 + w] = s2; }
    __syncthreads();
    s1 = sh[0] + sh[1] + sh[2] + sh[3];
    s2 = sh[4] + sh[5] + sh[6] + sh[7];
    float mu  = s1 * (1.0f / DIMv);
    float var = s2 * (1.0f / DIMv) - mu * mu;
    float rs  = rsqrtf(var + EPSv);
    __half* orow = out + r * (long)K2_DIM;
    #pragma unroll
    for (int q = 0; q < 3; q++) {
        int c = t + q * 128;
        float vv = (q == 0 ? v0 : (q == 1 ? v1 : v2));
        float y = (vv - mu) * rs * g[c] + bta[c];
        __half hi, lo; split2h(y, hi, lo);
        orow[c]        = hi;
        orow[DIMv + c] = lo;
    }
}

// ---------------- attention v3: float4 smem, no online max, SEL diag mask ----------------
__global__ void __launch_bounds__(224)
attn3(const float* __restrict__ scale)
{
    __shared__ float4 Ks[Nv][8];
    __shared__ float4 Vs[Nv][8];
    int h = blockIdx.x % Hv;
    int b = blockIdx.x / Hv;
    const float* base = g_qkv + (size_t)b * Nv * (3 * INNERv) + h * DHv;

    for (int idx = threadIdx.x; idx < Nv * 8; idx += 224) {
        int r = idx >> 3;
        int c = idx & 7;
        const float* row = base + (size_t)r * (3 * INNERv);
        Ks[r][c] = *(const float4*)(row + INNERv + c * 4);
        Vs[r][c] = *(const float4*)(row + 2 * INNERv + c * 4);
    }
    __syncthreads();

    int i = threadIdx.x;
    if (i >= Nv) return;
    float sc = scale[h];
    const float* qrow = base + (size_t)i * (3 * INNERv);
    float4 q[8];
    #pragma unroll
    for (int c = 0; c < 8; c++) {
        float4 v = *(const float4*)(qrow + c * 4);
        q[c] = make_float4(v.x * sc, v.y * sc, v.z * sc, v.w * sc);
    }

    float s = 0.0f;
    float4 acc[8];
    #pragma unroll
    for (int c = 0; c < 8; c++) acc[c] = make_float4(0.f, 0.f, 0.f, 0.f);

    #pragma unroll 2
    for (int j = 0; j < Nv; j++) {
        // dot with 4 parallel chains
        float d0 = 0.f, d1 = 0.f, d2 = 0.f, d3 = 0.f;
        #pragma unroll
        for (int c = 0; c < 8; c++) {
            float4 k = Ks[j][c];
            d0 = fmaf(q[c].x, k.x, d0);
            d1 = fmaf(q[c].y, k.y, d1);
            d2 = fmaf(q[c].z, k.z, d2);
            d3 = fmaf(q[c].w, k.w, d3);
        }
        float d = (d0 + d1) + (d2 + d3);
        float p = (j == i) ? 0.0f : __expf(d);   // SEL, no divergence
        s += p;
        #pragma unroll
        for (int c = 0; c < 8; c++) {
            float4 v = Vs[j][c];
            acc[c].x = fmaf(p, v.x, acc[c].x);
            acc[c].y = fmaf(p, v.y, acc[c].y);
            acc[c].z = fmaf(p, v.z, acc[c].z);
            acc[c].w = fmaf(p, v.w, acc[c].w);
        }
    }

    float inv = 1.0f / s;
    __half* o = a2_o + (size_t)(b * Nv + i) * K2_DIM + h * DHv;
    #pragma unroll
    for (int c = 0; c < 8; c++) {
        float vv[4] = {acc[c].x * inv, acc[c].y * inv, acc[c].z * inv, acc[c].w * inv};
        #pragma unroll
        for (int u = 0; u < 4; u++) {
            __half hi, lo; split2h(vv[u], hi, lo);
            o[c * 4 + u]        = hi;
            o[DIMv + c * 4 + u] = lo;
        }
    }
}

// ---------------- HMMA split-fp16 GEMM: C = A2[M,2K] * W2[N,2K]^T ----------------
// CTA tile 128x128, 8 warps of 64x32, BK=32, 4-stage cp.async ring, single sync.
#define FLAG_GELU  1
#define FLAG_REMAP 2
#define FLAG_SPLIT 4
#define HSTRIDE 40                       // halves per smem row (80B, conflict-free)
#define HS_B    (128 * HSTRIDE * 2)      // 10240B
#define STAGEB  (2 * 128 * HSTRIDE * 2)  // 20480B
#define NSTAGE  4
#define SMEM_DYN (NSTAGE * STAGEB)       // 81920B

__device__ __forceinline__ void store_pair(
    float v0, float v1, int orow, int gn, int Nn,
    const float* bias, const float* resid, const float* pos,
    float* Cf, __half* Cs, int flags)
{
    if (bias) { v0 += bias[gn]; v1 += bias[gn + 1]; }
    if (flags & FLAG_GELU) { v0 = gelu_exact(v0); v1 = gelu_exact(v1); }
    if (pos) {
        const float* pp = pos + (size_t)(orow % Nv) * Nn + gn;
        v0 += pp[0]; v1 += pp[1];
    }
    if (resid) {
        const float* rr = resid + (size_t)orow * Nn + gn;
        v0 += rr[0]; v1 += rr[1];
    }
    if (flags & FLAG_SPLIT) {
        __half h0, l0, h1, l1;
        split2h(v0, h0, l0); split2h(v1, h1, l1);
        __half* p = Cs + (size_t)orow * 2 * Nn + gn;
        *(__half2*)(p)      = __halves2half2(h0, h1);
        *(__half2*)(p + Nn) = __halves2half2(l0, l1);
    } else {
        *(float2*)(Cf + (size_t)orow * Nn + gn) = make_float2(v0, v1);
    }
}

__global__ void __launch_bounds__(256, 2)
hm_gemm(const __half* __restrict__ A, const __half* __restrict__ W,
        const float* __restrict__ bias, const float* __restrict__ resid,
        const float* __restrict__ pos, float* __restrict__ Cf,
        __half* __restrict__ Cs,
        int M, int Nn, int K2, int flags)
{
    extern __shared__ __align__(16) char sm[];
    uint32_t sbase = smem_u32(sm);
    int tid = threadIdx.x, lane = tid & 31, wid = tid >> 5;
    int m0 = blockIdx.y * 128, n0 = blockIdx.x * 128;
    int wr = wid >> 2, wc = wid & 3;     // warp tile: 64(M) x 32(N)

    float c[4][4][4];
    #pragma unroll
    for (int i = 0; i < 4; i++)
        #pragma unroll
        for (int j = 0; j < 4; j++)
            #pragma unroll
            for (int q = 0; q < 4; q++) c[i][j][q] = 0.0f;

    const int rbase = tid >> 2;          // 0..63
    const int kseg  = (tid & 3) * 8;     // halves

    const int nk = K2 / 32;

    auto load_stage = [&](int slot, int ch) {
        uint32_t sa = sbase + slot * STAGEB;
        int kk = ch * 32;
        #pragma unroll
        for (int i = 0; i < 2; i++) {
            int r = rbase + i * 64;
            uint32_t dst = sa + (uint32_t)(r * HSTRIDE + kseg) * 2;
            const void* src = A + (size_t)(m0 + r) * K2 + kk + kseg;
            cp16(dst, src, (m0 + r < M) ? 16u : 0u);
        }
        #pragma unroll
        for (int i = 0; i < 2; i++) {
            int r = rbase + i * 64;
            uint32_t dst = sa + HS_B + (uint32_t)(r * HSTRIDE + kseg) * 2;
            const void* src = W + (size_t)(n0 + r) * K2 + kk + kseg;
            cp16(dst, src, (n0 + r < Nn) ? 16u : 0u);
        }
        CP_COMMIT();
    };

    #pragma unroll
    for (int s = 0; s < NSTAGE - 1; s++) load_stage(s, s);   // nk >= 3 always

    for (int ch = 0; ch < nk; ch++) {
        CP_WAIT2();
        __syncthreads();
        if (ch + NSTAGE - 1 < nk) load_stage((ch + NSTAGE - 1) & 3, ch + NSTAGE - 1);
        else CP_COMMIT();

        uint32_t sa = sbase + (ch & 3) * STAGEB;
        #pragma unroll
        for (int ko = 0; ko < 2; ko++) {
            int col = ko * 16 + ((lane >> 4) << 3);
            uint32_t a[4][4];
            #pragma unroll
            for (int mf = 0; mf < 4; mf++) {
                int row = wr * 64 + mf * 16 + (lane & 15);
                ldsm4(a[mf], sa + (uint32_t)(row * HSTRIDE + col) * 2);
            }
            uint32_t b[2][4];
            #pragma unroll
            for (int p = 0; p < 2; p++) {
                int row = wc * 32 + p * 16 + (lane & 15);
                ldsm4(b[p], sa + HS_B + (uint32_t)(row * HSTRIDE + col) * 2);
            }
            #pragma unroll
            for (int mf = 0; mf < 4; mf++)
                #pragma unroll
                for (int nf = 0; nf < 4; nf++) {
                    int p = nf >> 1, q = nf & 1;
                    mma16816(c[mf][nf], a[mf], b[p][q], b[p][2 + q]);
                }
        }
    }

    // ---- epilogue ----
    #pragma unroll
    for (int mf = 0; mf < 4; mf++) {
        int r0 = m0 + wr * 64 + mf * 16 + (lane >> 2);
        #pragma unroll
        for (int nf = 0; nf < 4; nf++) {
            int gn = n0 + wc * 32 + nf * 8 + (lane & 3) * 2;
            if (gn >= Nn) continue;
            if (r0 < M) {
                int orow = r0;
                if (flags & FLAG_REMAP) { int b = r0 / NPv; orow = r0 + b + 1; }
                store_pair(c[mf][nf][0], c[mf][nf][1], orow, gn, Nn,
                           bias, resid, pos, Cf, Cs, flags);
            }
            int r1 = r0 + 8;
            if (r1 < M) {
                int orow = r1;
                if (flags & FLAG_REMAP) { int b = r1 / NPv; orow = r1 + b + 1; }
                store_pair(c[mf][nf][2], c[mf][nf][3], orow, gn, Nn,
                           bias, resid, pos, Cf, Cs, flags);
            }
        }
    }
}

// ---------------- host side ----------------
static inline void run_hm(const __half* A, const __half* W,
                          const float* bias, const float* resid, const float* pos,
                          float* Cf, __half* Cs,
                          int M, int Nn, int K2, int flags)
{
    dim3 grid((Nn + 127) / 128, (M + 127) / 128);
    hm_gemm<<<grid, 256, SMEM_DYN>>>(A, W, bias, resid, pos, Cf, Cs, M, Nn, K2, flags);
}

extern "C" void kernel_launch(void* const* d_in, const int* in_sizes, int n_in,
                              void* d_out, int out_size)
{
    const float* img     = (const float*)d_in[0];
    const float* patch_w = (const float*)d_in[1];
    const float* patch_b = (const float*)d_in[2];
    const float* pos_emb = (const float*)d_in[3];
    const float* cls_tok = (const float*)d_in[4];
    const float* ln1_g   = (const float*)d_in[5];
    const float* ln1_b   = (const float*)d_in[6];
    const float* qkv_w   = (const float*)d_in[7];
    const float* scale   = (const float*)d_in[8];
    const float* out_w   = (const float*)d_in[9];
    const float* out_b   = (const float*)d_in[10];
    const float* ln2_g   = (const float*)d_in[11];
    const float* ln2_b   = (const float*)d_in[12];
    const float* ff_w1   = (const float*)d_in[13];
    const float* ff_b1   = (const float*)d_in[14];
    const float* ff_w2   = (const float*)d_in[15];
    const float* ff_b2   = (const float*)d_in[16];
    const float* lnf_g   = (const float*)d_in[17];
    const float* lnf_b   = (const float*)d_in[18];
    const float* head_w  = (const float*)d_in[19];
    const float* head_b  = (const float*)d_in[20];

    cudaFuncSetAttribute(hm_gemm, cudaFuncAttributeMaxDynamicSharedMemorySize, SMEM_DYN);

    float *xp, *qkvp;
    __half *a2p, *a2hp, *a2op, *a2fp, *a2cp;
    __half *w2p, *w2q, *w2o, *w2f1, *w2f2, *w2h;
    cudaGetSymbolAddress((void**)&xp,   g_x);
    cudaGetSymbolAddress((void**)&qkvp, g_qkv);
    cudaGetSymbolAddress((void**)&a2p,  a2_patch);
    cudaGetSymbolAddress((void**)&a2hp, a2_h);
    cudaGetSymbolAddress((void**)&a2op, a2_o);
    cudaGetSymbolAddress((void**)&a2fp, a2_ff);
    cudaGetSymbolAddress((void**)&a2cp, a2_cls);
    cudaGetSymbolAddress((void**)&w2p,  w2_patch);
    cudaGetSymbolAddress((void**)&w2q,  w2_qkv);
    cudaGetSymbolAddress((void**)&w2o,  w2_out);
    cudaGetSymbolAddress((void**)&w2f1, w2_ff1);
    cudaGetSymbolAddress((void**)&w2f2, w2_ff2);
    cudaGetSymbolAddress((void**)&w2h,  w2_head);

    {
        int n = Bv * IMGv * IMGv;
        mean_kernel<<<(n + 255) / 256, 256>>>(img);
        int np = MP * PDv;
        patch_build_kernel<<<(np + 255) / 256, 256>>>(img);
        int nw = DIMv * PDv;
        convw_kernel<<<dim3((nw + 255) / 256, 1), 256>>>(patch_w, w2p, DIMv, PDv);
    }
    run_hm(a2p, w2p, patch_b, nullptr, pos_emb, xp, nullptr,
           MP, DIMv, K2_PD, FLAG_REMAP);
    cls_init_kernel<<<Bv, DIMv>>>(cls_tok, pos_emb);

    {
        int n;
        n = 3 * INNERv * DIMv;
        convw_kernel<<<dim3((n + 255) / 256, DEPTHv), 256>>>(qkv_w, w2q, 3 * INNERv, DIMv);
        n = DIMv * INNERv;
        convw_kernel<<<dim3((n + 255) / 256, DEPTHv), 256>>>(out_w, w2o, DIMv, INNERv);
        n = MLPv * DIMv;
        convw_kernel<<<dim3((n + 255) / 256, DEPTHv), 256>>>(ff_w1, w2f1, MLPv, DIMv);
        n = DIMv * MLPv;
        convw_kernel<<<dim3((n + 255) / 256, DEPTHv), 256>>>(ff_w2, w2f2, DIMv, MLPv);
        n = NCLSv * DIMv;
        convw_kernel<<<dim3((n + 255) / 256, 1), 256>>>(head_w, w2h, NCLSv, DIMv);
    }

    for (int L = 0; L < DEPTHv; L++) {
        ln_split_kernel<<<TOK, 128>>>(xp, ln1_g + L * DIMv, ln1_b + L * DIMv, a2hp, DIMv);
        run_hm(a2hp, w2q + (size_t)L * 3 * INNERv * K2_DIM, nullptr, nullptr, nullptr,
               qkvp, nullptr, TOK, 3 * INNERv, K2_DIM, 0);
        attn3<<<Bv * Hv, 224>>>(scale + L * Hv);
        run_hm(a2op, w2o + (size_t)L * DIMv * K2_DIM, out_b + L * DIMv, xp, nullptr,
               xp, nullptr, TOK, DIMv, K2_DIM, 0);
        ln_split_kernel<<<TOK, 128>>>(xp, ln2_g + L * DIMv, ln2_b + L * DIMv, a2hp, DIMv);
        run_hm(a2hp, w2f1 + (size_t)L * MLPv * K2_DIM, ff_b1 + L * MLPv, nullptr, nullptr,
               nullptr, a2fp, TOK, MLPv, K2_DIM, FLAG_GELU | FLAG_SPLIT);
        run_hm(a2fp, w2f2 + (size_t)L * DIMv * K2_MLP, ff_b2 + L * DIMv, xp, nullptr,
               xp, nullptr, TOK, DIMv, K2_MLP, 0);
    }

    // final LN on cls rows (row b = x[b*197*384]) -> split, then head
    ln_split_kernel<<<Bv, 128>>>(xp, lnf_g, lnf_b, a2cp, (long)Nv * DIMv);
    run_hm(a2cp, w2h, head_b, nullptr, nullptr, (float*)d_out, nullptr,
           Bv, NCLSv, K2_DIM, 0);
}